// round 1
// baseline (speedup 1.0000x reference)
#include <cuda_runtime.h>
#include <math.h>

// Problem constants
#define CB 2
#define CT 2048
#define CD 1024
#define CH 16
#define CK 64
#define CDFF 4096
#define CBT (CB*CT)   // 4096 rows

// -------- scratch (device globals; no allocations allowed) --------
__device__ float g_h1[(size_t)CBT*CD];            // LN1 output
__device__ float g_qkv[3][(size_t)CB*CH*CT*CK];   // q,k,v in [B,H,T,K]
__device__ float g_oc[(size_t)CBT*CD];            // attn out, concat [B,T,D]
__device__ float g_x2[(size_t)CBT*CD];            // residual after attn
__device__ float g_h2[(size_t)CBT*CD];            // LN2 output
__device__ float g_ff[(size_t)CBT*CDFF];          // FF1 activations

// ============================ LayerNorm ============================
__device__ __forceinline__ void ln_body(const float* __restrict__ in,
                                        const float* __restrict__ g,
                                        const float* __restrict__ be,
                                        float* __restrict__ out) {
    int row = blockIdx.x;
    int tid = threadIdx.x;
    const float* xr = in + (size_t)row * CD;
    float v[4];
    float s = 0.f;
#pragma unroll
    for (int i = 0; i < 4; i++) { v[i] = xr[tid + i*256]; s += v[i]; }

    __shared__ float red[8];
#pragma unroll
    for (int o = 16; o; o >>= 1) s += __shfl_xor_sync(0xffffffffu, s, o);
    if ((tid & 31) == 0) red[tid >> 5] = s;
    __syncthreads();
    float tot = 0.f;
#pragma unroll
    for (int i = 0; i < 8; i++) tot += red[i];
    float mu = tot * (1.f / CD);

    float s2 = 0.f;
#pragma unroll
    for (int i = 0; i < 4; i++) { float d = v[i] - mu; s2 += d * d; }
    __syncthreads();   // protect red reuse
#pragma unroll
    for (int o = 16; o; o >>= 1) s2 += __shfl_xor_sync(0xffffffffu, s2, o);
    if ((tid & 31) == 0) red[tid >> 5] = s2;
    __syncthreads();
    float tot2 = 0.f;
#pragma unroll
    for (int i = 0; i < 8; i++) tot2 += red[i];
    float rstd = rsqrtf(tot2 * (1.f / CD) + 1e-5f);

    float* orow = out + (size_t)row * CD;
#pragma unroll
    for (int i = 0; i < 4; i++) {
        int c = tid + i*256;
        orow[c] = (v[i] - mu) * rstd * g[c] + be[c];
    }
}

__global__ void k_ln1(const float* __restrict__ x, const float* __restrict__ g,
                      const float* __restrict__ be) {
    ln_body(x, g, be, g_h1);
}
__global__ void k_ln2(const float* __restrict__ g, const float* __restrict__ be) {
    ln_body(g_x2, g, be, g_h2);
}

// ======================= shared SGEMM tile core ====================
// 64x64 output tile, 256 threads, 4x4 microtile per thread, K chunks of 16.
__device__ __forceinline__ void gemm_core(const float* __restrict__ A, int lda,
                                          const float* __restrict__ Bm, int ldb,
                                          int kdim, float acc[4][4]) {
    __shared__ float As[16][68];
    __shared__ float Bs[16][68];
    int tid = threadIdx.x;
    int tx = tid & 15, ty = tid >> 4;

    for (int k0 = 0; k0 < kdim; k0 += 16) {
        __syncthreads();
        // A tile: 64 rows x 16 k
#pragma unroll
        for (int i = 0; i < 4; i++) {
            int m = (tid >> 4) + i * 16;
            As[tid & 15][m] = A[(size_t)m * lda + k0 + (tid & 15)];
        }
        // B tile: 16 k x 64 cols
#pragma unroll
        for (int i = 0; i < 4; i++) {
            int kk = (tid >> 6) + i * 4;
            Bs[kk][tid & 63] = Bm[(size_t)(k0 + kk) * ldb + (tid & 63)];
        }
        __syncthreads();
#pragma unroll
        for (int kk = 0; kk < 16; kk++) {
            float4 a4 = *(const float4*)&As[kk][ty * 4];
            float4 b4 = *(const float4*)&Bs[kk][tx * 4];
            float av[4] = {a4.x, a4.y, a4.z, a4.w};
            float bv[4] = {b4.x, b4.y, b4.z, b4.w};
#pragma unroll
            for (int i = 0; i < 4; i++)
#pragma unroll
                for (int j = 0; j < 4; j++)
                    acc[i][j] += av[i] * bv[j];
        }
    }
}

// ============================== QKV ================================
// grid: (BT/64, H, 3); per head GEMM [4096,1024]x[1024,64] -> [B,H,T,K]
__global__ void k_qkv(const float* __restrict__ Wq, const float* __restrict__ Wk,
                      const float* __restrict__ Wv) {
    const float* W = (blockIdx.z == 0) ? Wq : (blockIdx.z == 1) ? Wk : Wv;
    W += (size_t)blockIdx.y * CD * CK;
    const float* A = g_h1 + (size_t)blockIdx.x * 64 * CD;
    float acc[4][4] = {};
    gemm_core(A, CD, W, CK, CD, acc);

    int tx = threadIdx.x & 15, ty = threadIdx.x >> 4;
    int b  = blockIdx.x / (CT / 64);
    int t0 = (blockIdx.x % (CT / 64)) * 64;
    float* C = g_qkv[blockIdx.z] + (((size_t)b * CH + blockIdx.y) * CT + t0) * CK;
#pragma unroll
    for (int i = 0; i < 4; i++)
#pragma unroll
        for (int j = 0; j < 4; j++)
            C[(size_t)(ty * 4 + i) * CK + tx * 4 + j] = acc[i][j];
}

// ========================= Flash attention =========================
// grid: (T/64, B*H); 256 threads; causal; online softmax.
#define ATTN_SMEM_BYTES (4 * 64 * 68 * 4)
__global__ void k_attn() {
    extern __shared__ float sm[];
    float* Qs = sm;                 // [64][68] layout [d][m]
    float* Ks = Qs + 64 * 68;       // [d][n]
    float* Vs = Ks + 64 * 68;       // [s][c]
    float* Ss = Vs + 64 * 68;       // [r][s]
    __shared__ float m_s[64], l_s[64], a_s[64];

    int tid = threadIdx.x, tx = tid & 15, ty = tid >> 4;
    int qb = blockIdx.x, bh = blockIdx.y;
    const float* Q  = g_qkv[0] + (size_t)bh * CT * CK;
    const float* Kp = g_qkv[1] + (size_t)bh * CT * CK;
    const float* Vp = g_qkv[2] + (size_t)bh * CT * CK;

    // load Q tile transposed, pre-scaled by 1/sqrt(64)
    {
        int m = tid >> 2, d0 = (tid & 3) * 16;
        const float* qr = Q + (size_t)(qb * 64 + m) * CK + d0;
#pragma unroll
        for (int i = 0; i < 16; i += 4) {
            float4 v4 = *(const float4*)(qr + i);
            Qs[(d0 + i + 0) * 68 + m] = v4.x * 0.125f;
            Qs[(d0 + i + 1) * 68 + m] = v4.y * 0.125f;
            Qs[(d0 + i + 2) * 68 + m] = v4.z * 0.125f;
            Qs[(d0 + i + 3) * 68 + m] = v4.w * 0.125f;
        }
    }
    if (tid < 64) { m_s[tid] = -INFINITY; l_s[tid] = 0.f; }

    float acc[4][4] = {};
    for (int kb = 0; kb <= qb; kb++) {
        __syncthreads();
        // load K (transposed) and V (natural)
        {
            int n = tid >> 2, d0 = (tid & 3) * 16;
            const float* kr = Kp + (size_t)(kb * 64 + n) * CK + d0;
            const float* vr = Vp + (size_t)(kb * 64 + n) * CK + d0;
#pragma unroll
            for (int i = 0; i < 16; i += 4) {
                float4 k4 = *(const float4*)(kr + i);
                Ks[(d0 + i + 0) * 68 + n] = k4.x;
                Ks[(d0 + i + 1) * 68 + n] = k4.y;
                Ks[(d0 + i + 2) * 68 + n] = k4.z;
                Ks[(d0 + i + 3) * 68 + n] = k4.w;
                float4 v4 = *(const float4*)(vr + i);
                Vs[n * 68 + d0 + i + 0] = v4.x;
                Vs[n * 68 + d0 + i + 1] = v4.y;
                Vs[n * 68 + d0 + i + 2] = v4.z;
                Vs[n * 68 + d0 + i + 3] = v4.w;
            }
        }
        __syncthreads();

        // S = Q K^T (64x64), 4x4 per thread
        float s[4][4] = {};
#pragma unroll
        for (int d = 0; d < 64; d++) {
            float4 a4 = *(const float4*)&Qs[d * 68 + ty * 4];
            float4 b4 = *(const float4*)&Ks[d * 68 + tx * 4];
            float av[4] = {a4.x, a4.y, a4.z, a4.w};
            float bv[4] = {b4.x, b4.y, b4.z, b4.w};
#pragma unroll
            for (int i = 0; i < 4; i++)
#pragma unroll
                for (int j = 0; j < 4; j++)
                    s[i][j] += av[i] * bv[j];
        }
        if (kb == qb) {
#pragma unroll
            for (int i = 0; i < 4; i++)
#pragma unroll
                for (int j = 0; j < 4; j++)
                    if (tx * 4 + j > ty * 4 + i) s[i][j] = -INFINITY;
        }
#pragma unroll
        for (int i = 0; i < 4; i++)
#pragma unroll
            for (int j = 0; j < 4; j++)
                Ss[(ty * 4 + i) * 68 + tx * 4 + j] = s[i][j];
        __syncthreads();

        // online softmax: 4 threads per row
        {
            int r = tid >> 2, c0 = (tid & 3) * 16;
            float mx = -INFINITY;
#pragma unroll
            for (int c = 0; c < 16; c++) mx = fmaxf(mx, Ss[r * 68 + c0 + c]);
            mx = fmaxf(mx, __shfl_xor_sync(0xffffffffu, mx, 1));
            mx = fmaxf(mx, __shfl_xor_sync(0xffffffffu, mx, 2));
            float mo = m_s[r];
            float mn = fmaxf(mo, mx);
            float sum = 0.f;
#pragma unroll
            for (int c = 0; c < 16; c++) {
                float p = __expf(Ss[r * 68 + c0 + c] - mn);
                Ss[r * 68 + c0 + c] = p;
                sum += p;
            }
            sum += __shfl_xor_sync(0xffffffffu, sum, 1);
            sum += __shfl_xor_sync(0xffffffffu, sum, 2);
            if ((tid & 3) == 0) {
                float al = __expf(mo - mn);
                a_s[r] = al;
                l_s[r] = l_s[r] * al + sum;
                m_s[r] = mn;
            }
        }
        __syncthreads();

        // rescale + P@V accumulate
#pragma unroll
        for (int i = 0; i < 4; i++) {
            float al = a_s[ty * 4 + i];
#pragma unroll
            for (int j = 0; j < 4; j++) acc[i][j] *= al;
        }
#pragma unroll
        for (int st = 0; st < 64; st++) {
            float4 b4 = *(const float4*)&Vs[st * 68 + tx * 4];
            float bv[4] = {b4.x, b4.y, b4.z, b4.w};
            float av[4];
#pragma unroll
            for (int i = 0; i < 4; i++) av[i] = Ss[(ty * 4 + i) * 68 + st];
#pragma unroll
            for (int i = 0; i < 4; i++)
#pragma unroll
                for (int j = 0; j < 4; j++)
                    acc[i][j] += av[i] * bv[j];
        }
    }

    // write concat output [B,T,H,K] == [BT,D]
    int b = bh / CH, h = bh % CH;
#pragma unroll
    for (int i = 0; i < 4; i++) {
        int t = qb * 64 + ty * 4 + i;
        float inv_l = 1.f / l_s[ty * 4 + i];
#pragma unroll
        for (int j = 0; j < 4; j++)
            g_oc[(((size_t)(b * CT + t)) * CH + h) * CK + tx * 4 + j] = acc[i][j] * inv_l;
    }
}

// ======================= Wo projection + residual ==================
__global__ void k_wo(const float* __restrict__ x, const float* __restrict__ Wo,
                     const float* __restrict__ bo) {
    const float* A = g_oc + (size_t)blockIdx.x * 64 * CD;
    const float* Bm = Wo + blockIdx.y * 64;
    float acc[4][4] = {};
    gemm_core(A, CD, Bm, CD, CD, acc);

    int tx = threadIdx.x & 15, ty = threadIdx.x >> 4;
#pragma unroll
    for (int i = 0; i < 4; i++) {
        size_t row = (size_t)blockIdx.x * 64 + ty * 4 + i;
#pragma unroll
        for (int j = 0; j < 4; j++) {
            int col = blockIdx.y * 64 + tx * 4 + j;
            g_x2[row * CD + col] = x[row * CD + col] + acc[i][j] + bo[col];
        }
    }
}

// =========================== FFN kernels ===========================
__global__ void k_ff1(const float* __restrict__ W1, const float* __restrict__ b1) {
    const float* A = g_h2 + (size_t)blockIdx.x * 64 * CD;
    const float* Bm = W1 + blockIdx.y * 64;
    float acc[4][4] = {};
    gemm_core(A, CD, Bm, CDFF, CD, acc);

    int tx = threadIdx.x & 15, ty = threadIdx.x >> 4;
#pragma unroll
    for (int i = 0; i < 4; i++) {
        size_t row = (size_t)blockIdx.x * 64 + ty * 4 + i;
#pragma unroll
        for (int j = 0; j < 4; j++) {
            int col = blockIdx.y * 64 + tx * 4 + j;
            float v = acc[i][j] + b1[col];
            g_ff[row * CDFF + col] = 0.5f * v * (1.f + erff(v * 0.70710678118654752f));
        }
    }
}

__global__ void k_ff2(const float* __restrict__ W2, const float* __restrict__ b2,
                      float* __restrict__ out) {
    const float* A = g_ff + (size_t)blockIdx.x * 64 * CDFF;
    const float* Bm = W2 + blockIdx.y * 64;
    float acc[4][4] = {};
    gemm_core(A, CDFF, Bm, CD, CDFF, acc);

    int tx = threadIdx.x & 15, ty = threadIdx.x >> 4;
#pragma unroll
    for (int i = 0; i < 4; i++) {
        size_t row = (size_t)blockIdx.x * 64 + ty * 4 + i;
#pragma unroll
        for (int j = 0; j < 4; j++) {
            int col = blockIdx.y * 64 + tx * 4 + j;
            out[row * CD + col] = g_x2[row * CD + col] + acc[i][j] + b2[col];
        }
    }
}

// ============================= launch ==============================
extern "C" void kernel_launch(void* const* d_in, const int* in_sizes, int n_in,
                              void* d_out, int out_size) {
    (void)in_sizes; (void)n_in; (void)out_size;
    const float* x   = (const float*)d_in[0];
    const float* Wq  = (const float*)d_in[1];
    const float* Wk  = (const float*)d_in[2];
    const float* Wv  = (const float*)d_in[3];
    const float* Wo  = (const float*)d_in[4];
    const float* bo  = (const float*)d_in[5];
    const float* W1  = (const float*)d_in[6];
    const float* b1  = (const float*)d_in[7];
    const float* W2  = (const float*)d_in[8];
    const float* b2  = (const float*)d_in[9];
    const float* g1  = (const float*)d_in[10];
    const float* be1 = (const float*)d_in[11];
    const float* g2  = (const float*)d_in[12];
    const float* be2 = (const float*)d_in[13];
    float* out = (float*)d_out;

    cudaFuncSetAttribute(k_attn, cudaFuncAttributeMaxDynamicSharedMemorySize,
                         ATTN_SMEM_BYTES);

    k_ln1<<<CBT, 256>>>(x, g1, be1);
    k_qkv<<<dim3(CBT / 64, CH, 3), 256>>>(Wq, Wk, Wv);
    k_attn<<<dim3(CT / 64, CB * CH), 256, ATTN_SMEM_BYTES>>>();
    k_wo<<<dim3(CBT / 64, CD / 64), 256>>>(x, Wo, bo);
    k_ln2<<<CBT, 256>>>(g2, be2);
    k_ff1<<<dim3(CBT / 64, CDFF / 64), 256>>>(W1, b1);
    k_ff2<<<dim3(CBT / 64, CD / 64), 256>>>(W2, b2, out);
}

// round 3
// speedup vs baseline: 2.1507x; 2.1507x over previous
#include <cuda_runtime.h>
#include <math.h>
#include <stdint.h>

// Problem constants
#define CB 2
#define CT 2048
#define CD 1024
#define CH 16
#define CK 64
#define CDFF 4096
#define CBT (CB*CT)   // 4096 rows

// -------- scratch (device globals; no allocations allowed) --------
__device__ float g_h1[(size_t)CBT*CD];            // LN1 output
__device__ float g_qkv[3][(size_t)CB*CH*CT*CK];   // q,k,v in [B,H,T,K]
__device__ float g_oc[(size_t)CBT*CD];            // attn out, concat [B,T,D]
__device__ float g_x2[(size_t)CBT*CD];            // residual after attn
__device__ float g_h2[(size_t)CBT*CD];            // LN2 output
__device__ float g_ff[(size_t)CBT*CDFF];          // FF1 activations
// transposed weights [N][K] K-major
__device__ float g_qkvwt[(size_t)3*CD*CD];        // 3072 x 1024
__device__ float g_wot[(size_t)CD*CD];            // 1024 x 1024
__device__ float g_w1t[(size_t)CDFF*CD];          // 4096 x 1024
__device__ float g_w2t[(size_t)CD*CDFF];          // 1024 x 4096

// ===================== helpers =======================
__device__ __forceinline__ uint32_t f2tf(float x) {
    uint32_t r;
    asm("cvt.rna.tf32.f32 %0, %1;" : "=r"(r) : "f"(x));
    return r;
}
__device__ __forceinline__ void mma_tf32_16n8k8(float d[4],
                                                const uint32_t a[4],
                                                const uint32_t b[2]) {
    asm volatile(
        "mma.sync.aligned.m16n8k8.row.col.f32.tf32.tf32.f32 "
        "{%0,%1,%2,%3}, {%4,%5,%6,%7}, {%8,%9}, {%0,%1,%2,%3};\n"
        : "+f"(d[0]), "+f"(d[1]), "+f"(d[2]), "+f"(d[3])
        : "r"(a[0]), "r"(a[1]), "r"(a[2]), "r"(a[3]), "r"(b[0]), "r"(b[1]));
}

// ===================== transposes (weights -> [N][K]) ==============
__device__ __forceinline__ void tr_body(const float* __restrict__ src,
                                        float* __restrict__ dst, int R, int C) {
    __shared__ float t[32][33];
    int c0 = blockIdx.x * 32, r0 = blockIdx.y * 32;
    int x = threadIdx.x, y = threadIdx.y;
#pragma unroll
    for (int i = 0; i < 32; i += 8) t[y + i][x] = src[(size_t)(r0 + y + i) * C + c0 + x];
    __syncthreads();
#pragma unroll
    for (int i = 0; i < 32; i += 8) dst[(size_t)(c0 + y + i) * R + r0 + x] = t[x][y + i];
}
__global__ void k_tr(const float* __restrict__ src, float* __restrict__ dst, int R, int C) {
    tr_body(src, dst, R, C);
}
__global__ void k_qkvw_tr(const float* __restrict__ Wq, const float* __restrict__ Wk,
                          const float* __restrict__ Wv) {
    int zh = blockIdx.z;
    const float* base = (zh < 16) ? Wq : (zh < 32) ? Wk : Wv;
    const float* src = base + (size_t)(zh & 15) * CD * CK;   // [1024][64]
    float* dst = g_qkvwt + (size_t)zh * CK * CD;             // [64][1024]
    tr_body(src, dst, CD, CK);
}

// ============================ LayerNorm ============================
__device__ __forceinline__ void ln_body(const float* __restrict__ in,
                                        const float* __restrict__ g,
                                        const float* __restrict__ be,
                                        float* __restrict__ out) {
    int row = blockIdx.x;
    int tid = threadIdx.x;
    const float* xr = in + (size_t)row * CD;
    float v[4];
    float s = 0.f;
#pragma unroll
    for (int i = 0; i < 4; i++) { v[i] = xr[tid + i*256]; s += v[i]; }

    __shared__ float red[8];
#pragma unroll
    for (int o = 16; o; o >>= 1) s += __shfl_xor_sync(0xffffffffu, s, o);
    if ((tid & 31) == 0) red[tid >> 5] = s;
    __syncthreads();
    float tot = 0.f;
#pragma unroll
    for (int i = 0; i < 8; i++) tot += red[i];
    float mu = tot * (1.f / CD);

    float s2 = 0.f;
#pragma unroll
    for (int i = 0; i < 4; i++) { float d = v[i] - mu; s2 += d * d; }
    __syncthreads();
#pragma unroll
    for (int o = 16; o; o >>= 1) s2 += __shfl_xor_sync(0xffffffffu, s2, o);
    if ((tid & 31) == 0) red[tid >> 5] = s2;
    __syncthreads();
    float tot2 = 0.f;
#pragma unroll
    for (int i = 0; i < 8; i++) tot2 += red[i];
    float rstd = rsqrtf(tot2 * (1.f / CD) + 1e-5f);

    float* orow = out + (size_t)row * CD;
#pragma unroll
    for (int i = 0; i < 4; i++) {
        int c = tid + i*256;
        orow[c] = (v[i] - mu) * rstd * g[c] + be[c];
    }
}
__global__ void k_ln1(const float* __restrict__ x, const float* __restrict__ g,
                      const float* __restrict__ be) { ln_body(x, g, be, g_h1); }
__global__ void k_ln2(const float* __restrict__ g, const float* __restrict__ be) {
    ln_body(g_x2, g, be, g_h2);
}

// ===================== tf32 mma.sync GEMM ==========================
// C[128 x 128] tile per CTA, 8 warps (2 M x 4 N), each warp 64x32 via
// 4x4 grid of m16n8k8 mma. A [M,K] K-major, B pre-transposed [N][K] K-major.
// smem chunk: 128 rows x 32 k, row stride 36 floats (conflict-free frags).
// MODE: 0=QKV scatter, 1=Wo(+x+bo), 2=FF1(+b1,gelu), 3=FF2(+res+b2)
#define KCH 32
#define SROW 36

template<int MODE>
__global__ void __launch_bounds__(256, 2) k_gemm(
    const float* __restrict__ A, int lda,
    const float* __restrict__ Bt, int kdim,
    const float* __restrict__ bias,
    const float* __restrict__ xres,
    float* __restrict__ out, int ldout)
{
    __shared__ uint32_t As[128 * SROW];
    __shared__ uint32_t Bs[128 * SROW];

    int tid = threadIdx.x, wid = tid >> 5, lane = tid & 31;
    int m0 = blockIdx.x * 128, n0 = blockIdx.y * 128;
    int wm = (wid >> 2) * 64, wn = (wid & 3) * 32;
    int gid = lane >> 2, tig = lane & 3;

    float acc[4][4][4];
#pragma unroll
    for (int i = 0; i < 4; i++)
#pragma unroll
        for (int j = 0; j < 4; j++)
#pragma unroll
            for (int q = 0; q < 4; q++) acc[i][j][q] = 0.f;

    int lrow = tid >> 3, lc4 = (tid & 7) * 4;
    const float* Ap = A + (size_t)(m0 + lrow) * lda + lc4;
    const float* Bp = Bt + (size_t)(n0 + lrow) * kdim + lc4;

    for (int k0 = 0; k0 < kdim; k0 += KCH) {
        float4 av[4], bv[4];
#pragma unroll
        for (int i = 0; i < 4; i++) {
            av[i] = *(const float4*)(Ap + (size_t)(i * 32) * lda);
            bv[i] = *(const float4*)(Bp + (size_t)(i * 32) * kdim);
        }
        Ap += KCH; Bp += KCH;
        __syncthreads();
#pragma unroll
        for (int i = 0; i < 4; i++) {
            uint32_t* as = &As[(lrow + i * 32) * SROW + lc4];
            as[0] = f2tf(av[i].x); as[1] = f2tf(av[i].y);
            as[2] = f2tf(av[i].z); as[3] = f2tf(av[i].w);
            uint32_t* bs = &Bs[(lrow + i * 32) * SROW + lc4];
            bs[0] = f2tf(bv[i].x); bs[1] = f2tf(bv[i].y);
            bs[2] = f2tf(bv[i].z); bs[3] = f2tf(bv[i].w);
        }
        __syncthreads();

#pragma unroll
        for (int kk = 0; kk < 4; kk++) {
            int kb = kk * 8 + tig;
            uint32_t a[4][4], b[4][2];
#pragma unroll
            for (int mt = 0; mt < 4; mt++) {
                int r = (wm + 16 * mt + gid) * SROW + kb;
                a[mt][0] = As[r];
                a[mt][1] = As[r + 8 * SROW];
                a[mt][2] = As[r + 4];
                a[mt][3] = As[r + 8 * SROW + 4];
            }
#pragma unroll
            for (int nt = 0; nt < 4; nt++) {
                int r = (wn + 8 * nt + gid) * SROW + kb;
                b[nt][0] = Bs[r];
                b[nt][1] = Bs[r + 4];
            }
#pragma unroll
            for (int mt = 0; mt < 4; mt++)
#pragma unroll
                for (int nt = 0; nt < 4; nt++)
                    mma_tf32_16n8k8(acc[mt][nt], a[mt], b[nt]);
        }
    }

    // fused epilogue: each c-frag covers (r, c0..c0+1) and (r+8, c0..c0+1)
#pragma unroll
    for (int mt = 0; mt < 4; mt++) {
#pragma unroll
        for (int half = 0; half < 2; half++) {
            int grow = m0 + wm + 16 * mt + gid + 8 * half;
#pragma unroll
            for (int nt = 0; nt < 4; nt++) {
                int gcol = n0 + wn + 8 * nt + 2 * tig;
                float v0 = acc[mt][nt][half * 2 + 0];
                float v1 = acc[mt][nt][half * 2 + 1];
                if (MODE == 0) {
                    int z = gcol >> 10, rem = gcol & 1023, h = rem >> 6, kk = rem & 63;
                    int b = grow >> 11, t = grow & 2047;
                    float* dst = &g_qkv[z][(((size_t)(b * CH + h) * CT) + t) * CK + kk];
                    dst[0] = v0; dst[1] = v1;
                } else if (MODE == 1 || MODE == 3) {
                    const float* xr = &xres[(size_t)grow * ldout + gcol];
                    float* dst = &out[(size_t)grow * ldout + gcol];
                    dst[0] = xr[0] + v0 + bias[gcol];
                    dst[1] = xr[1] + v1 + bias[gcol + 1];
                } else {
                    float u0 = v0 + bias[gcol];
                    float u1 = v1 + bias[gcol + 1];
                    float* dst = &out[(size_t)grow * ldout + gcol];
                    dst[0] = 0.5f * u0 * (1.f + erff(u0 * 0.70710678118654752f));
                    dst[1] = 0.5f * u1 * (1.f + erff(u1 * 0.70710678118654752f));
                }
            }
        }
    }
}

// ========================= Flash attention =========================
#define ATTN_SMEM_BYTES (4 * 64 * 68 * 4)
__global__ void k_attn() {
    extern __shared__ float smf[];
    float* Qs = smf;
    float* Ks = Qs + 64 * 68;
    float* Vs = Ks + 64 * 68;
    float* Ss = Vs + 64 * 68;
    __shared__ float m_s[64], l_s[64], a_s[64];

    int tid = threadIdx.x, tx = tid & 15, ty = tid >> 4;
    int qb = blockIdx.x, bh = blockIdx.y;
    const float* Q  = g_qkv[0] + (size_t)bh * CT * CK;
    const float* Kp = g_qkv[1] + (size_t)bh * CT * CK;
    const float* Vp = g_qkv[2] + (size_t)bh * CT * CK;

    {
        int m = tid >> 2, d0 = (tid & 3) * 16;
        const float* qr = Q + (size_t)(qb * 64 + m) * CK + d0;
#pragma unroll
        for (int i = 0; i < 16; i += 4) {
            float4 v4 = *(const float4*)(qr + i);
            Qs[(d0 + i + 0) * 68 + m] = v4.x * 0.125f;
            Qs[(d0 + i + 1) * 68 + m] = v4.y * 0.125f;
            Qs[(d0 + i + 2) * 68 + m] = v4.z * 0.125f;
            Qs[(d0 + i + 3) * 68 + m] = v4.w * 0.125f;
        }
    }
    if (tid < 64) { m_s[tid] = -INFINITY; l_s[tid] = 0.f; }

    float acc[4][4] = {};
    for (int kb = 0; kb <= qb; kb++) {
        __syncthreads();
        {
            int n = tid >> 2, d0 = (tid & 3) * 16;
            const float* kr = Kp + (size_t)(kb * 64 + n) * CK + d0;
            const float* vr = Vp + (size_t)(kb * 64 + n) * CK + d0;
#pragma unroll
            for (int i = 0; i < 16; i += 4) {
                float4 k4 = *(const float4*)(kr + i);
                Ks[(d0 + i + 0) * 68 + n] = k4.x;
                Ks[(d0 + i + 1) * 68 + n] = k4.y;
                Ks[(d0 + i + 2) * 68 + n] = k4.z;
                Ks[(d0 + i + 3) * 68 + n] = k4.w;
                float4 v4 = *(const float4*)(vr + i);
                Vs[n * 68 + d0 + i + 0] = v4.x;
                Vs[n * 68 + d0 + i + 1] = v4.y;
                Vs[n * 68 + d0 + i + 2] = v4.z;
                Vs[n * 68 + d0 + i + 3] = v4.w;
            }
        }
        __syncthreads();

        float sv[4][4] = {};
#pragma unroll
        for (int d = 0; d < 64; d++) {
            float4 a4 = *(const float4*)&Qs[d * 68 + ty * 4];
            float4 b4 = *(const float4*)&Ks[d * 68 + tx * 4];
            float avx[4] = {a4.x, a4.y, a4.z, a4.w};
            float bvx[4] = {b4.x, b4.y, b4.z, b4.w};
#pragma unroll
            for (int i = 0; i < 4; i++)
#pragma unroll
                for (int j = 0; j < 4; j++)
                    sv[i][j] += avx[i] * bvx[j];
        }
        if (kb == qb) {
#pragma unroll
            for (int i = 0; i < 4; i++)
#pragma unroll
                for (int j = 0; j < 4; j++)
                    if (tx * 4 + j > ty * 4 + i) sv[i][j] = -INFINITY;
        }
#pragma unroll
        for (int i = 0; i < 4; i++)
#pragma unroll
            for (int j = 0; j < 4; j++)
                Ss[(ty * 4 + i) * 68 + tx * 4 + j] = sv[i][j];
        __syncthreads();

        {
            int rr = tid >> 2, cc0 = (tid & 3) * 16;
            float mx = -INFINITY;
#pragma unroll
            for (int c = 0; c < 16; c++) mx = fmaxf(mx, Ss[rr * 68 + cc0 + c]);
            mx = fmaxf(mx, __shfl_xor_sync(0xffffffffu, mx, 1));
            mx = fmaxf(mx, __shfl_xor_sync(0xffffffffu, mx, 2));
            float mo = m_s[rr];
            float mn = fmaxf(mo, mx);
            float sum = 0.f;
#pragma unroll
            for (int c = 0; c < 16; c++) {
                float p = __expf(Ss[rr * 68 + cc0 + c] - mn);
                Ss[rr * 68 + cc0 + c] = p;
                sum += p;
            }
            sum += __shfl_xor_sync(0xffffffffu, sum, 1);
            sum += __shfl_xor_sync(0xffffffffu, sum, 2);
            if ((tid & 3) == 0) {
                float al = __expf(mo - mn);
                a_s[rr] = al;
                l_s[rr] = l_s[rr] * al + sum;
                m_s[rr] = mn;
            }
        }
        __syncthreads();

#pragma unroll
        for (int i = 0; i < 4; i++) {
            float al = a_s[ty * 4 + i];
#pragma unroll
            for (int j = 0; j < 4; j++) acc[i][j] *= al;
        }
#pragma unroll
        for (int st = 0; st < 64; st++) {
            float4 b4 = *(const float4*)&Vs[st * 68 + tx * 4];
            float bvx[4] = {b4.x, b4.y, b4.z, b4.w};
            float avx[4];
#pragma unroll
            for (int i = 0; i < 4; i++) avx[i] = Ss[(ty * 4 + i) * 68 + st];
#pragma unroll
            for (int i = 0; i < 4; i++)
#pragma unroll
                for (int j = 0; j < 4; j++)
                    acc[i][j] += avx[i] * bvx[j];
        }
    }

    int b = bh / CH, h = bh % CH;
#pragma unroll
    for (int i = 0; i < 4; i++) {
        int t = qb * 64 + ty * 4 + i;
        float inv_l = 1.f / l_s[ty * 4 + i];
#pragma unroll
        for (int j = 0; j < 4; j++)
            g_oc[(((size_t)(b * CT + t)) * CH + h) * CK + tx * 4 + j] = acc[i][j] * inv_l;
    }
}

// ============================= launch ==============================
extern "C" void kernel_launch(void* const* d_in, const int* in_sizes, int n_in,
                              void* d_out, int out_size) {
    (void)in_sizes; (void)n_in; (void)out_size;
    const float* x   = (const float*)d_in[0];
    const float* Wq  = (const float*)d_in[1];
    const float* Wk  = (const float*)d_in[2];
    const float* Wv  = (const float*)d_in[3];
    const float* Wo  = (const float*)d_in[4];
    const float* bo  = (const float*)d_in[5];
    const float* W1  = (const float*)d_in[6];
    const float* b1  = (const float*)d_in[7];
    const float* W2  = (const float*)d_in[8];
    const float* b2  = (const float*)d_in[9];
    const float* g1  = (const float*)d_in[10];
    const float* be1 = (const float*)d_in[11];
    const float* g2  = (const float*)d_in[12];
    const float* be2 = (const float*)d_in[13];
    float* out = (float*)d_out;

    cudaFuncSetAttribute(k_attn, cudaFuncAttributeMaxDynamicSharedMemorySize, ATTN_SMEM_BYTES);

    float* g_qkvwt_p; cudaGetSymbolAddress((void**)&g_qkvwt_p, g_qkvwt);
    float* g_wot_p;   cudaGetSymbolAddress((void**)&g_wot_p, g_wot);
    float* g_w1t_p;   cudaGetSymbolAddress((void**)&g_w1t_p, g_w1t);
    float* g_w2t_p;   cudaGetSymbolAddress((void**)&g_w2t_p, g_w2t);
    float* g_h1_p;    cudaGetSymbolAddress((void**)&g_h1_p, g_h1);
    float* g_oc_p;    cudaGetSymbolAddress((void**)&g_oc_p, g_oc);
    float* g_x2_p;    cudaGetSymbolAddress((void**)&g_x2_p, g_x2);
    float* g_h2_p;    cudaGetSymbolAddress((void**)&g_h2_p, g_h2);
    float* g_ff_p;    cudaGetSymbolAddress((void**)&g_ff_p, g_ff);

    // weight transposes -> [N][K]
    k_qkvw_tr<<<dim3(CK / 32, CD / 32, 48), dim3(32, 8)>>>(Wq, Wk, Wv);
    k_tr<<<dim3(CD / 32, CD / 32), dim3(32, 8)>>>(Wo, g_wot_p, CD, CD);
    k_tr<<<dim3(CDFF / 32, CD / 32), dim3(32, 8)>>>(W1, g_w1t_p, CD, CDFF);
    k_tr<<<dim3(CD / 32, CDFF / 32), dim3(32, 8)>>>(W2, g_w2t_p, CDFF, CD);

    k_ln1<<<CBT, 256>>>(x, g1, be1);
    // QKV: [4096 x 3072]
    k_gemm<0><<<dim3(CBT / 128, 3 * CD / 128), 256>>>(
        g_h1_p, CD, g_qkvwt_p, CD, nullptr, nullptr, nullptr, 0);
    k_attn<<<dim3(CT / 64, CB * CH), 256, ATTN_SMEM_BYTES>>>();
    // Wo + residual
    k_gemm<1><<<dim3(CBT / 128, CD / 128), 256>>>(
        g_oc_p, CD, g_wot_p, CD, bo, x, g_x2_p, CD);
    k_ln2<<<CBT, 256>>>(g2, be2);
    // FF1 + gelu
    k_gemm<2><<<dim3(CBT / 128, CDFF / 128), 256>>>(
        g_h2_p, CD, g_w1t_p, CD, b1, nullptr, g_ff_p, CDFF);
    // FF2 + residual -> out
    k_gemm<3><<<dim3(CBT / 128, CD / 128), 256>>>(
        g_ff_p, CDFF, g_w2t_p, CDFF, b2, g_x2_p, out, CD);
}

// round 4
// speedup vs baseline: 2.4553x; 1.1416x over previous
#include <cuda_runtime.h>
#include <math.h>
#include <stdint.h>

// Problem constants
#define CB 2
#define CT 2048
#define CD 1024
#define CH 16
#define CK 64
#define CDFF 4096
#define CBT (CB*CT)   // 4096 rows

// -------- scratch (device globals; no allocations allowed) --------
__device__ float g_h1[(size_t)CBT*CD];            // LN1 output (tf32)
__device__ float g_qkv[3][(size_t)CB*CH*CT*CK];   // q,k,v in [B,H,T,K] (fp32)
__device__ float g_oc[(size_t)CBT*CD];            // attn out concat (tf32)
__device__ float g_x2[(size_t)CBT*CD];            // residual after attn (fp32)
__device__ float g_h2[(size_t)CBT*CD];            // LN2 output (tf32)
__device__ float g_ff[(size_t)CBT*CDFF];          // FF1 activations (tf32)
// transposed weights [N][K] K-major (tf32)
__device__ float g_qkvwt[(size_t)3*CD*CD];        // 3072 x 1024
__device__ float g_wot[(size_t)CD*CD];            // 1024 x 1024
__device__ float g_w1t[(size_t)CDFF*CD];          // 4096 x 1024
__device__ float g_w2t[(size_t)CD*CDFF];          // 1024 x 4096

// ===================== helpers =======================
__device__ __forceinline__ uint32_t f2tf(float x) {
    uint32_t r;
    asm("cvt.rna.tf32.f32 %0, %1;" : "=r"(r) : "f"(x));
    return r;
}
__device__ __forceinline__ float f2tff(float x) {
    return __uint_as_float(f2tf(x));
}
__device__ __forceinline__ uint32_t smem_u32(const void* p) {
    uint32_t a;
    asm("{ .reg .u64 t; cvta.to.shared.u64 t, %1; cvt.u32.u64 %0, t; }" : "=r"(a) : "l"(p));
    return a;
}
__device__ __forceinline__ void cp_async16(uint32_t s, const void* g) {
    asm volatile("cp.async.cg.shared.global [%0], [%1], 16;" :: "r"(s), "l"(g));
}
__device__ __forceinline__ void cp_commit() {
    asm volatile("cp.async.commit_group;");
}
__device__ __forceinline__ void mma_tf32_16n8k8(float d[4],
                                                const uint32_t a[4],
                                                const uint32_t b[2]) {
    asm volatile(
        "mma.sync.aligned.m16n8k8.row.col.f32.tf32.tf32.f32 "
        "{%0,%1,%2,%3}, {%4,%5,%6,%7}, {%8,%9}, {%0,%1,%2,%3};\n"
        : "+f"(d[0]), "+f"(d[1]), "+f"(d[2]), "+f"(d[3])
        : "r"(a[0]), "r"(a[1]), "r"(a[2]), "r"(a[3]), "r"(b[0]), "r"(b[1]));
}

// ===================== transposes (weights -> [N][K], tf32) ========
__device__ __forceinline__ void tr_body(const float* __restrict__ src,
                                        float* __restrict__ dst, int R, int C) {
    __shared__ float t[32][33];
    int c0 = blockIdx.x * 32, r0 = blockIdx.y * 32;
    int x = threadIdx.x, y = threadIdx.y;
#pragma unroll
    for (int i = 0; i < 32; i += 8) t[y + i][x] = src[(size_t)(r0 + y + i) * C + c0 + x];
    __syncthreads();
#pragma unroll
    for (int i = 0; i < 32; i += 8)
        dst[(size_t)(c0 + y + i) * R + r0 + x] = f2tff(t[x][y + i]);
}
__global__ void k_tr(const float* __restrict__ src, float* __restrict__ dst, int R, int C) {
    tr_body(src, dst, R, C);
}
__global__ void k_qkvw_tr(const float* __restrict__ Wq, const float* __restrict__ Wk,
                          const float* __restrict__ Wv) {
    int zh = blockIdx.z;
    const float* base = (zh < 16) ? Wq : (zh < 32) ? Wk : Wv;
    const float* src = base + (size_t)(zh & 15) * CD * CK;   // [1024][64]
    float* dst = g_qkvwt + (size_t)zh * CK * CD;             // [64][1024]
    tr_body(src, dst, CD, CK);
}

// ============================ LayerNorm ============================
// outputs tf32-rounded values (only feed GEMMs)
__device__ __forceinline__ void ln_body(const float* __restrict__ in,
                                        const float* __restrict__ g,
                                        const float* __restrict__ be,
                                        float* __restrict__ out) {
    int row = blockIdx.x;
    int tid = threadIdx.x;
    const float* xr = in + (size_t)row * CD;
    float v[4];
    float s = 0.f;
#pragma unroll
    for (int i = 0; i < 4; i++) { v[i] = xr[tid + i*256]; s += v[i]; }

    __shared__ float red[8];
#pragma unroll
    for (int o = 16; o; o >>= 1) s += __shfl_xor_sync(0xffffffffu, s, o);
    if ((tid & 31) == 0) red[tid >> 5] = s;
    __syncthreads();
    float tot = 0.f;
#pragma unroll
    for (int i = 0; i < 8; i++) tot += red[i];
    float mu = tot * (1.f / CD);

    float s2 = 0.f;
#pragma unroll
    for (int i = 0; i < 4; i++) { float d = v[i] - mu; s2 += d * d; }
    __syncthreads();
#pragma unroll
    for (int o = 16; o; o >>= 1) s2 += __shfl_xor_sync(0xffffffffu, s2, o);
    if ((tid & 31) == 0) red[tid >> 5] = s2;
    __syncthreads();
    float tot2 = 0.f;
#pragma unroll
    for (int i = 0; i < 8; i++) tot2 += red[i];
    float rstd = rsqrtf(tot2 * (1.f / CD) + 1e-5f);

    float* orow = out + (size_t)row * CD;
#pragma unroll
    for (int i = 0; i < 4; i++) {
        int c = tid + i*256;
        orow[c] = f2tff((v[i] - mu) * rstd * g[c] + be[c]);
    }
}
__global__ void k_ln1(const float* __restrict__ x, const float* __restrict__ g,
                      const float* __restrict__ be) { ln_body(x, g, be, g_h1); }
__global__ void k_ln2(const float* __restrict__ g, const float* __restrict__ be) {
    ln_body(g_x2, g, be, g_h2);
}

// ===================== tf32 mma.sync GEMM ==========================
// C[128 x 128] tile per CTA, 8 warps (2 M x 4 N), each warp 64x32 via
// 4x4 grid of m16n8k8 mma. Inputs pre-converted to tf32 -> cp.async copy.
// Double-buffered smem, K chunks of 32.
// MODE: 0=QKV scatter, 1=Wo(+x+bo), 2=FF1(+b1,gelu->tf32), 3=FF2(+res+b2)
#define KCH 32
#define SROW 36
#define STG_W (128 * SROW)              // words per matrix per stage
#define GEMM_SMEM (4 * STG_W * 4)       // bytes: 2 stages x (A+B)

template<int MODE>
__global__ void __launch_bounds__(256, 2) k_gemm(
    const float* __restrict__ A, int lda,
    const float* __restrict__ Bt, int kdim,
    const float* __restrict__ bias,
    const float* __restrict__ xres,
    float* __restrict__ out, int ldout)
{
    extern __shared__ uint32_t smw[];
    uint32_t* Asm = smw;                 // [2][128][SROW]
    uint32_t* Bsm = smw + 2 * STG_W;

    int tid = threadIdx.x, wid = tid >> 5, lane = tid & 31;
    int m0 = blockIdx.x * 128, n0 = blockIdx.y * 128;
    int wm = (wid >> 2) * 64, wn = (wid & 3) * 32;
    int gid = lane >> 2, tig = lane & 3;

    float acc[4][4][4];
#pragma unroll
    for (int i = 0; i < 4; i++)
#pragma unroll
        for (int j = 0; j < 4; j++)
#pragma unroll
            for (int q = 0; q < 4; q++) acc[i][j][q] = 0.f;

    int lrow = tid >> 3, lc4 = (tid & 7) * 4;
    const float* Ap = A + (size_t)(m0 + lrow) * lda + lc4;
    const float* Bp = Bt + (size_t)(n0 + lrow) * kdim + lc4;
    uint32_t a_s0 = smem_u32(Asm) + (uint32_t)(lrow * SROW + lc4) * 4;
    uint32_t b_s0 = smem_u32(Bsm) + (uint32_t)(lrow * SROW + lc4) * 4;

    const int nch = kdim >> 5;

    // prefetch chunk 0 into stage 0
#pragma unroll
    for (int i = 0; i < 4; i++) {
        cp_async16(a_s0 + (uint32_t)(i * 32 * SROW) * 4, Ap + (size_t)(i * 32) * lda);
        cp_async16(b_s0 + (uint32_t)(i * 32 * SROW) * 4, Bp + (size_t)(i * 32) * kdim);
    }
    cp_commit();

    for (int c = 0; c < nch; c++) {
        int p = c & 1;
        if (c + 1 < nch) {
            int pn = (c + 1) & 1;
            const float* An = Ap + (c + 1) * KCH;
            const float* Bn = Bp + (c + 1) * KCH;
            uint32_t asn = a_s0 + (uint32_t)(pn * STG_W) * 4;
            uint32_t bsn = b_s0 + (uint32_t)(pn * STG_W) * 4;
#pragma unroll
            for (int i = 0; i < 4; i++) {
                cp_async16(asn + (uint32_t)(i * 32 * SROW) * 4, An + (size_t)(i * 32) * lda);
                cp_async16(bsn + (uint32_t)(i * 32 * SROW) * 4, Bn + (size_t)(i * 32) * kdim);
            }
            cp_commit();
            asm volatile("cp.async.wait_group 1;");
        } else {
            asm volatile("cp.async.wait_group 0;");
        }
        __syncthreads();

        const uint32_t* As = Asm + p * STG_W;
        const uint32_t* Bs = Bsm + p * STG_W;
#pragma unroll
        for (int kk = 0; kk < 4; kk++) {
            int kb = kk * 8 + tig;
            uint32_t a[4][4], b[4][2];
#pragma unroll
            for (int mt = 0; mt < 4; mt++) {
                int r = (wm + 16 * mt + gid) * SROW + kb;
                a[mt][0] = As[r];
                a[mt][1] = As[r + 8 * SROW];
                a[mt][2] = As[r + 4];
                a[mt][3] = As[r + 8 * SROW + 4];
            }
#pragma unroll
            for (int nt = 0; nt < 4; nt++) {
                int r = (wn + 8 * nt + gid) * SROW + kb;
                b[nt][0] = Bs[r];
                b[nt][1] = Bs[r + 4];
            }
#pragma unroll
            for (int mt = 0; mt < 4; mt++)
#pragma unroll
                for (int nt = 0; nt < 4; nt++)
                    mma_tf32_16n8k8(acc[mt][nt], a[mt], b[nt]);
        }
        __syncthreads();
    }

    // fused epilogue: each c-frag covers (r, c0..c0+1) and (r+8, c0..c0+1)
#pragma unroll
    for (int mt = 0; mt < 4; mt++) {
#pragma unroll
        for (int half = 0; half < 2; half++) {
            int grow = m0 + wm + 16 * mt + gid + 8 * half;
#pragma unroll
            for (int nt = 0; nt < 4; nt++) {
                int gcol = n0 + wn + 8 * nt + 2 * tig;
                float v0 = acc[mt][nt][half * 2 + 0];
                float v1 = acc[mt][nt][half * 2 + 1];
                if (MODE == 0) {
                    int z = gcol >> 10, rem = gcol & 1023, h = rem >> 6, kk = rem & 63;
                    int b = grow >> 11, t = grow & 2047;
                    float* dst = &g_qkv[z][(((size_t)(b * CH + h) * CT) + t) * CK + kk];
                    dst[0] = v0; dst[1] = v1;
                } else if (MODE == 1 || MODE == 3) {
                    const float* xr = &xres[(size_t)grow * ldout + gcol];
                    float* dst = &out[(size_t)grow * ldout + gcol];
                    dst[0] = xr[0] + v0 + bias[gcol];
                    dst[1] = xr[1] + v1 + bias[gcol + 1];
                } else {
                    float u0 = v0 + bias[gcol];
                    float u1 = v1 + bias[gcol + 1];
                    float* dst = &out[(size_t)grow * ldout + gcol];
                    dst[0] = f2tff(0.5f * u0 * (1.f + erff(u0 * 0.70710678118654752f)));
                    dst[1] = f2tff(0.5f * u1 * (1.f + erff(u1 * 0.70710678118654752f)));
                }
            }
        }
    }
}

// ========================= Flash attention =========================
#define ATTN_SMEM_BYTES (4 * 64 * 68 * 4)
__global__ void k_attn() {
    extern __shared__ float smf[];
    float* Qs = smf;
    float* Ks = Qs + 64 * 68;
    float* Vs = Ks + 64 * 68;
    float* Ss = Vs + 64 * 68;
    __shared__ float m_s[64], l_s[64], a_s[64];

    int tid = threadIdx.x, tx = tid & 15, ty = tid >> 4;
    int qb = blockIdx.x, bh = blockIdx.y;
    const float* Q  = g_qkv[0] + (size_t)bh * CT * CK;
    const float* Kp = g_qkv[1] + (size_t)bh * CT * CK;
    const float* Vp = g_qkv[2] + (size_t)bh * CT * CK;

    {
        int m = tid >> 2, d0 = (tid & 3) * 16;
        const float* qr = Q + (size_t)(qb * 64 + m) * CK + d0;
#pragma unroll
        for (int i = 0; i < 16; i += 4) {
            float4 v4 = *(const float4*)(qr + i);
            Qs[(d0 + i + 0) * 68 + m] = v4.x * 0.125f;
            Qs[(d0 + i + 1) * 68 + m] = v4.y * 0.125f;
            Qs[(d0 + i + 2) * 68 + m] = v4.z * 0.125f;
            Qs[(d0 + i + 3) * 68 + m] = v4.w * 0.125f;
        }
    }
    if (tid < 64) { m_s[tid] = -INFINITY; l_s[tid] = 0.f; }

    float acc[4][4] = {};
    for (int kb = 0; kb <= qb; kb++) {
        __syncthreads();
        {
            int n = tid >> 2, d0 = (tid & 3) * 16;
            const float* kr = Kp + (size_t)(kb * 64 + n) * CK + d0;
            const float* vr = Vp + (size_t)(kb * 64 + n) * CK + d0;
#pragma unroll
            for (int i = 0; i < 16; i += 4) {
                float4 k4 = *(const float4*)(kr + i);
                Ks[(d0 + i + 0) * 68 + n] = k4.x;
                Ks[(d0 + i + 1) * 68 + n] = k4.y;
                Ks[(d0 + i + 2) * 68 + n] = k4.z;
                Ks[(d0 + i + 3) * 68 + n] = k4.w;
                float4 v4 = *(const float4*)(vr + i);
                Vs[n * 68 + d0 + i + 0] = v4.x;
                Vs[n * 68 + d0 + i + 1] = v4.y;
                Vs[n * 68 + d0 + i + 2] = v4.z;
                Vs[n * 68 + d0 + i + 3] = v4.w;
            }
        }
        __syncthreads();

        float sv[4][4] = {};
#pragma unroll
        for (int d = 0; d < 64; d++) {
            float4 a4 = *(const float4*)&Qs[d * 68 + ty * 4];
            float4 b4 = *(const float4*)&Ks[d * 68 + tx * 4];
            float avx[4] = {a4.x, a4.y, a4.z, a4.w};
            float bvx[4] = {b4.x, b4.y, b4.z, b4.w};
#pragma unroll
            for (int i = 0; i < 4; i++)
#pragma unroll
                for (int j = 0; j < 4; j++)
                    sv[i][j] += avx[i] * bvx[j];
        }
        if (kb == qb) {
#pragma unroll
            for (int i = 0; i < 4; i++)
#pragma unroll
                for (int j = 0; j < 4; j++)
                    if (tx * 4 + j > ty * 4 + i) sv[i][j] = -INFINITY;
        }
#pragma unroll
        for (int i = 0; i < 4; i++)
#pragma unroll
            for (int j = 0; j < 4; j++)
                Ss[(ty * 4 + i) * 68 + tx * 4 + j] = sv[i][j];
        __syncthreads();

        {
            int rr = tid >> 2, cc0 = (tid & 3) * 16;
            float mx = -INFINITY;
#pragma unroll
            for (int c = 0; c < 16; c++) mx = fmaxf(mx, Ss[rr * 68 + cc0 + c]);
            mx = fmaxf(mx, __shfl_xor_sync(0xffffffffu, mx, 1));
            mx = fmaxf(mx, __shfl_xor_sync(0xffffffffu, mx, 2));
            float mo = m_s[rr];
            float mn = fmaxf(mo, mx);
            float sum = 0.f;
#pragma unroll
            for (int c = 0; c < 16; c++) {
                float p = __expf(Ss[rr * 68 + cc0 + c] - mn);
                Ss[rr * 68 + cc0 + c] = p;
                sum += p;
            }
            sum += __shfl_xor_sync(0xffffffffu, sum, 1);
            sum += __shfl_xor_sync(0xffffffffu, sum, 2);
            if ((tid & 3) == 0) {
                float al = __expf(mo - mn);
                a_s[rr] = al;
                l_s[rr] = l_s[rr] * al + sum;
                m_s[rr] = mn;
            }
        }
        __syncthreads();

#pragma unroll
        for (int i = 0; i < 4; i++) {
            float al = a_s[ty * 4 + i];
#pragma unroll
            for (int j = 0; j < 4; j++) acc[i][j] *= al;
        }
#pragma unroll
        for (int st = 0; st < 64; st++) {
            float4 b4 = *(const float4*)&Vs[st * 68 + tx * 4];
            float bvx[4] = {b4.x, b4.y, b4.z, b4.w};
            float avx[4];
#pragma unroll
            for (int i = 0; i < 4; i++) avx[i] = Ss[(ty * 4 + i) * 68 + st];
#pragma unroll
            for (int i = 0; i < 4; i++)
#pragma unroll
                for (int j = 0; j < 4; j++)
                    acc[i][j] += avx[i] * bvx[j];
        }
    }

    int b = bh / CH, h = bh % CH;
#pragma unroll
    for (int i = 0; i < 4; i++) {
        int t = qb * 64 + ty * 4 + i;
        float inv_l = 1.f / l_s[ty * 4 + i];
#pragma unroll
        for (int j = 0; j < 4; j++)
            g_oc[(((size_t)(b * CT + t)) * CH + h) * CK + tx * 4 + j] =
                f2tff(acc[i][j] * inv_l);
    }
}

// ============================= launch ==============================
extern "C" void kernel_launch(void* const* d_in, const int* in_sizes, int n_in,
                              void* d_out, int out_size) {
    (void)in_sizes; (void)n_in; (void)out_size;
    const float* x   = (const float*)d_in[0];
    const float* Wq  = (const float*)d_in[1];
    const float* Wk  = (const float*)d_in[2];
    const float* Wv  = (const float*)d_in[3];
    const float* Wo  = (const float*)d_in[4];
    const float* bo  = (const float*)d_in[5];
    const float* W1  = (const float*)d_in[6];
    const float* b1  = (const float*)d_in[7];
    const float* W2  = (const float*)d_in[8];
    const float* b2  = (const float*)d_in[9];
    const float* g1  = (const float*)d_in[10];
    const float* be1 = (const float*)d_in[11];
    const float* g2  = (const float*)d_in[12];
    const float* be2 = (const float*)d_in[13];
    float* out = (float*)d_out;

    cudaFuncSetAttribute(k_attn, cudaFuncAttributeMaxDynamicSharedMemorySize, ATTN_SMEM_BYTES);
    cudaFuncSetAttribute(k_gemm<0>, cudaFuncAttributeMaxDynamicSharedMemorySize, GEMM_SMEM);
    cudaFuncSetAttribute(k_gemm<1>, cudaFuncAttributeMaxDynamicSharedMemorySize, GEMM_SMEM);
    cudaFuncSetAttribute(k_gemm<2>, cudaFuncAttributeMaxDynamicSharedMemorySize, GEMM_SMEM);
    cudaFuncSetAttribute(k_gemm<3>, cudaFuncAttributeMaxDynamicSharedMemorySize, GEMM_SMEM);

    float* g_qkvwt_p; cudaGetSymbolAddress((void**)&g_qkvwt_p, g_qkvwt);
    float* g_wot_p;   cudaGetSymbolAddress((void**)&g_wot_p, g_wot);
    float* g_w1t_p;   cudaGetSymbolAddress((void**)&g_w1t_p, g_w1t);
    float* g_w2t_p;   cudaGetSymbolAddress((void**)&g_w2t_p, g_w2t);
    float* g_h1_p;    cudaGetSymbolAddress((void**)&g_h1_p, g_h1);
    float* g_oc_p;    cudaGetSymbolAddress((void**)&g_oc_p, g_oc);
    float* g_x2_p;    cudaGetSymbolAddress((void**)&g_x2_p, g_x2);
    float* g_h2_p;    cudaGetSymbolAddress((void**)&g_h2_p, g_h2);
    float* g_ff_p;    cudaGetSymbolAddress((void**)&g_ff_p, g_ff);

    // weight transposes -> [N][K] tf32
    k_qkvw_tr<<<dim3(CK / 32, CD / 32, 48), dim3(32, 8)>>>(Wq, Wk, Wv);
    k_tr<<<dim3(CD / 32, CD / 32), dim3(32, 8)>>>(Wo, g_wot_p, CD, CD);
    k_tr<<<dim3(CDFF / 32, CD / 32), dim3(32, 8)>>>(W1, g_w1t_p, CD, CDFF);
    k_tr<<<dim3(CD / 32, CDFF / 32), dim3(32, 8)>>>(W2, g_w2t_p, CDFF, CD);

    k_ln1<<<CBT, 256>>>(x, g1, be1);
    // QKV: [4096 x 3072]
    k_gemm<0><<<dim3(CBT / 128, 3 * CD / 128), 256, GEMM_SMEM>>>(
        g_h1_p, CD, g_qkvwt_p, CD, nullptr, nullptr, nullptr, 0);
    k_attn<<<dim3(CT / 64, CB * CH), 256, ATTN_SMEM_BYTES>>>();
    // Wo + residual
    k_gemm<1><<<dim3(CBT / 128, CD / 128), 256, GEMM_SMEM>>>(
        g_oc_p, CD, g_wot_p, CD, bo, x, g_x2_p, CD);
    k_ln2<<<CBT, 256>>>(g2, be2);
    // FF1 + gelu
    k_gemm<2><<<dim3(CBT / 128, CDFF / 128), 256, GEMM_SMEM>>>(
        g_h2_p, CD, g_w1t_p, CD, b1, nullptr, g_ff_p, CDFF);
    // FF2 + residual -> out
    k_gemm<3><<<dim3(CBT / 128, CD / 128), 256, GEMM_SMEM>>>(
        g_ff_p, CDFF, g_w2t_p, CDFF, b2, g_x2_p, out, CD);
}

// round 6
// speedup vs baseline: 3.5579x; 1.4490x over previous
#include <cuda_runtime.h>
#include <math.h>
#include <stdint.h>

// Problem constants
#define CB 2
#define CT 2048
#define CD 1024
#define CH 16
#define CK 64
#define CDFF 4096
#define CBT (CB*CT)   // 4096 rows

// -------- scratch (device globals; no allocations allowed) --------
__device__ float g_h1[(size_t)CBT*CD];            // LN1 output (tf32)
__device__ float g_qkv[3][(size_t)CB*CH*CT*CK];   // q,k,v in [B,H,T,K] (fp32)
__device__ float g_oc[(size_t)CBT*CD];            // attn out concat (tf32)
__device__ float g_x2[(size_t)CBT*CD];            // residual after attn (fp32)
__device__ float g_h2[(size_t)CBT*CD];            // LN2 output (tf32)
__device__ float g_ff[(size_t)CBT*CDFF];          // FF1 activations (tf32)
// transposed weights [N][K] K-major (tf32)
__device__ float g_qkvwt[(size_t)3*CD*CD];        // 3072 x 1024
__device__ float g_wot[(size_t)CD*CD];            // 1024 x 1024
__device__ float g_w1t[(size_t)CDFF*CD];          // 4096 x 1024
__device__ float g_w2t[(size_t)CD*CDFF];          // 1024 x 4096

// ===================== helpers =======================
__device__ __forceinline__ uint32_t f2tf(float x) {
    uint32_t r;
    asm("cvt.rna.tf32.f32 %0, %1;" : "=r"(r) : "f"(x));
    return r;
}
__device__ __forceinline__ float f2tff(float x) {
    return __uint_as_float(f2tf(x));
}
__device__ __forceinline__ uint32_t smem_u32(const void* p) {
    uint32_t a;
    asm("{ .reg .u64 t; cvta.to.shared.u64 t, %1; cvt.u32.u64 %0, t; }" : "=r"(a) : "l"(p));
    return a;
}
__device__ __forceinline__ void cp_async16(uint32_t s, const void* g) {
    asm volatile("cp.async.cg.shared.global [%0], [%1], 16;" :: "r"(s), "l"(g));
}
__device__ __forceinline__ void cp_commit() {
    asm volatile("cp.async.commit_group;");
}
__device__ __forceinline__ void mma_tf32_16n8k8(float d[4],
                                                const uint32_t a[4],
                                                const uint32_t b[2]) {
    asm volatile(
        "mma.sync.aligned.m16n8k8.row.col.f32.tf32.tf32.f32 "
        "{%0,%1,%2,%3}, {%4,%5,%6,%7}, {%8,%9}, {%0,%1,%2,%3};\n"
        : "+f"(d[0]), "+f"(d[1]), "+f"(d[2]), "+f"(d[3])
        : "r"(a[0]), "r"(a[1]), "r"(a[2]), "r"(a[3]), "r"(b[0]), "r"(b[1]));
}

// ===================== transposes (weights -> [N][K], tf32) ========
__device__ __forceinline__ void tr_body(const float* __restrict__ src,
                                        float* __restrict__ dst, int R, int C) {
    __shared__ float t[32][33];
    int c0 = blockIdx.x * 32, r0 = blockIdx.y * 32;
    int x = threadIdx.x, y = threadIdx.y;
#pragma unroll
    for (int i = 0; i < 32; i += 8) t[y + i][x] = src[(size_t)(r0 + y + i) * C + c0 + x];
    __syncthreads();
#pragma unroll
    for (int i = 0; i < 32; i += 8)
        dst[(size_t)(c0 + y + i) * R + r0 + x] = f2tff(t[x][y + i]);
}
__global__ void k_tr(const float* __restrict__ src, float* __restrict__ dst, int R, int C) {
    tr_body(src, dst, R, C);
}
__global__ void k_qkvw_tr(const float* __restrict__ Wq, const float* __restrict__ Wk,
                          const float* __restrict__ Wv) {
    int zh = blockIdx.z;
    const float* base = (zh < 16) ? Wq : (zh < 32) ? Wk : Wv;
    const float* src = base + (size_t)(zh & 15) * CD * CK;   // [1024][64]
    float* dst = g_qkvwt + (size_t)zh * CK * CD;             // [64][1024]
    tr_body(src, dst, CD, CK);
}

// ============================ LayerNorm ============================
__device__ __forceinline__ void ln_body(const float* __restrict__ in,
                                        const float* __restrict__ g,
                                        const float* __restrict__ be,
                                        float* __restrict__ out) {
    int row = blockIdx.x;
    int tid = threadIdx.x;
    const float* xr = in + (size_t)row * CD;
    float v[4];
    float s = 0.f;
#pragma unroll
    for (int i = 0; i < 4; i++) { v[i] = xr[tid + i*256]; s += v[i]; }

    __shared__ float red[8];
#pragma unroll
    for (int o = 16; o; o >>= 1) s += __shfl_xor_sync(0xffffffffu, s, o);
    if ((tid & 31) == 0) red[tid >> 5] = s;
    __syncthreads();
    float tot = 0.f;
#pragma unroll
    for (int i = 0; i < 8; i++) tot += red[i];
    float mu = tot * (1.f / CD);

    float s2 = 0.f;
#pragma unroll
    for (int i = 0; i < 4; i++) { float d = v[i] - mu; s2 += d * d; }
    __syncthreads();
#pragma unroll
    for (int o = 16; o; o >>= 1) s2 += __shfl_xor_sync(0xffffffffu, s2, o);
    if ((tid & 31) == 0) red[tid >> 5] = s2;
    __syncthreads();
    float tot2 = 0.f;
#pragma unroll
    for (int i = 0; i < 8; i++) tot2 += red[i];
    float rstd = rsqrtf(tot2 * (1.f / CD) + 1e-5f);

    float* orow = out + (size_t)row * CD;
#pragma unroll
    for (int i = 0; i < 4; i++) {
        int c = tid + i*256;
        orow[c] = f2tff((v[i] - mu) * rstd * g[c] + be[c]);
    }
}
__global__ void k_ln1(const float* __restrict__ x, const float* __restrict__ g,
                      const float* __restrict__ be) { ln_body(x, g, be, g_h1); }
__global__ void k_ln2(const float* __restrict__ g, const float* __restrict__ be) {
    ln_body(g_x2, g, be, g_h2);
}

// ===================== tf32 mma.sync GEMM ==========================
#define KCH 32
#define SROW 36
#define STG_W (128 * SROW)
#define GEMM_SMEM (4 * STG_W * 4)

template<int MODE>
__global__ void __launch_bounds__(256, 2) k_gemm(
    const float* __restrict__ A, int lda,
    const float* __restrict__ Bt, int kdim,
    const float* __restrict__ bias,
    const float* __restrict__ xres,
    float* __restrict__ out, int ldout)
{
    extern __shared__ uint32_t smw[];
    uint32_t* Asm = smw;
    uint32_t* Bsm = smw + 2 * STG_W;

    int tid = threadIdx.x, wid = tid >> 5, lane = tid & 31;
    int m0 = blockIdx.x * 128, n0 = blockIdx.y * 128;
    int wm = (wid >> 2) * 64, wn = (wid & 3) * 32;
    int gid = lane >> 2, tig = lane & 3;

    float acc[4][4][4];
#pragma unroll
    for (int i = 0; i < 4; i++)
#pragma unroll
        for (int j = 0; j < 4; j++)
#pragma unroll
            for (int q = 0; q < 4; q++) acc[i][j][q] = 0.f;

    int lrow = tid >> 3, lc4 = (tid & 7) * 4;
    const float* Ap = A + (size_t)(m0 + lrow) * lda + lc4;
    const float* Bp = Bt + (size_t)(n0 + lrow) * kdim + lc4;
    uint32_t a_s0 = smem_u32(Asm) + (uint32_t)(lrow * SROW + lc4) * 4;
    uint32_t b_s0 = smem_u32(Bsm) + (uint32_t)(lrow * SROW + lc4) * 4;

    const int nch = kdim >> 5;

#pragma unroll
    for (int i = 0; i < 4; i++) {
        cp_async16(a_s0 + (uint32_t)(i * 32 * SROW) * 4, Ap + (size_t)(i * 32) * lda);
        cp_async16(b_s0 + (uint32_t)(i * 32 * SROW) * 4, Bp + (size_t)(i * 32) * kdim);
    }
    cp_commit();

    for (int c = 0; c < nch; c++) {
        int p = c & 1;
        if (c + 1 < nch) {
            int pn = (c + 1) & 1;
            const float* An = Ap + (c + 1) * KCH;
            const float* Bn = Bp + (c + 1) * KCH;
            uint32_t asn = a_s0 + (uint32_t)(pn * STG_W) * 4;
            uint32_t bsn = b_s0 + (uint32_t)(pn * STG_W) * 4;
#pragma unroll
            for (int i = 0; i < 4; i++) {
                cp_async16(asn + (uint32_t)(i * 32 * SROW) * 4, An + (size_t)(i * 32) * lda);
                cp_async16(bsn + (uint32_t)(i * 32 * SROW) * 4, Bn + (size_t)(i * 32) * kdim);
            }
            cp_commit();
            asm volatile("cp.async.wait_group 1;");
        } else {
            asm volatile("cp.async.wait_group 0;");
        }
        __syncthreads();

        const uint32_t* As = Asm + p * STG_W;
        const uint32_t* Bs = Bsm + p * STG_W;
#pragma unroll
        for (int kk = 0; kk < 4; kk++) {
            int kb = kk * 8 + tig;
            uint32_t a[4][4], b[4][2];
#pragma unroll
            for (int mt = 0; mt < 4; mt++) {
                int r = (wm + 16 * mt + gid) * SROW + kb;
                a[mt][0] = As[r];
                a[mt][1] = As[r + 8 * SROW];
                a[mt][2] = As[r + 4];
                a[mt][3] = As[r + 8 * SROW + 4];
            }
#pragma unroll
            for (int nt = 0; nt < 4; nt++) {
                int r = (wn + 8 * nt + gid) * SROW + kb;
                b[nt][0] = Bs[r];
                b[nt][1] = Bs[r + 4];
            }
#pragma unroll
            for (int mt = 0; mt < 4; mt++)
#pragma unroll
                for (int nt = 0; nt < 4; nt++)
                    mma_tf32_16n8k8(acc[mt][nt], a[mt], b[nt]);
        }
        __syncthreads();
    }

#pragma unroll
    for (int mt = 0; mt < 4; mt++) {
#pragma unroll
        for (int half = 0; half < 2; half++) {
            int grow = m0 + wm + 16 * mt + gid + 8 * half;
#pragma unroll
            for (int nt = 0; nt < 4; nt++) {
                int gcol = n0 + wn + 8 * nt + 2 * tig;
                float v0 = acc[mt][nt][half * 2 + 0];
                float v1 = acc[mt][nt][half * 2 + 1];
                if (MODE == 0) {
                    int z = gcol >> 10, rem = gcol & 1023, h = rem >> 6, kk = rem & 63;
                    int b = grow >> 11, t = grow & 2047;
                    float* dst = &g_qkv[z][(((size_t)(b * CH + h) * CT) + t) * CK + kk];
                    dst[0] = v0; dst[1] = v1;
                } else if (MODE == 1 || MODE == 3) {
                    const float* xr = &xres[(size_t)grow * ldout + gcol];
                    float* dst = &out[(size_t)grow * ldout + gcol];
                    dst[0] = xr[0] + v0 + bias[gcol];
                    dst[1] = xr[1] + v1 + bias[gcol + 1];
                } else {
                    float u0 = v0 + bias[gcol];
                    float u1 = v1 + bias[gcol + 1];
                    float* dst = &out[(size_t)grow * ldout + gcol];
                    dst[0] = f2tff(0.5f * u0 * (1.f + erff(u0 * 0.70710678118654752f)));
                    dst[1] = f2tff(0.5f * u1 * (1.f + erff(u1 * 0.70710678118654752f)));
                }
            }
        }
    }
}

// ================ Flash attention on mma.sync tf32 =================
// CTA: 64 queries x one (b,h). 128 threads / 4 warps; warp owns 16 rows.
// smem: Ks [64 keys][68] (B-layout [n][k]), Vt [64 d][68] (B-layout),
//       Ps [64 rows][68] (P tiles; also Q staging).
#define ASTR 68
#define ATTN_SMEM_BYTES ((2 * 64 * ASTR + 64 * ASTR) * 4)

__global__ void __launch_bounds__(128) k_attn_mma() {
    extern __shared__ float sm[];
    float* Ks = sm;                  // [64][ASTR]
    float* Vt = sm + 64 * ASTR;      // [64][ASTR]
    float* Ps = sm + 2 * 64 * ASTR;  // [64][ASTR]

    int tid = threadIdx.x, wid = tid >> 5, lane = tid & 31;
    int gid = lane >> 2, tig = lane & 3;
    int qi = blockIdx.x, bh = blockIdx.y;
    int q0 = qi * 64;

    const float* Q  = g_qkv[0] + (size_t)bh * CT * CK;
    const float* Kp = g_qkv[1] + (size_t)bh * CT * CK;
    const float* Vp = g_qkv[2] + (size_t)bh * CT * CK;

    // stage Q (scaled, tf32) into Ps, then load Q fragments to registers
#pragma unroll
    for (int i = 0; i < 8; i++) {
        int idx = tid + i * 128;
        int r = idx >> 4, c4 = (idx & 15) << 2;
        float4 v = *(const float4*)(Q + (size_t)(q0 + r) * CK + c4);
        float4 w;
        w.x = f2tff(v.x * 0.125f); w.y = f2tff(v.y * 0.125f);
        w.z = f2tff(v.z * 0.125f); w.w = f2tff(v.w * 0.125f);
        *(float4*)&Ps[r * ASTR + c4] = w;
    }
    __syncthreads();

    int rA = wid * 16 + gid;         // local row A; row B = rA + 8
    uint32_t qf[8][4];
    const uint32_t* Pu = (const uint32_t*)Ps;
#pragma unroll
    for (int kk = 0; kk < 8; kk++) {
        int base = rA * ASTR + kk * 8 + tig;
        qf[kk][0] = Pu[base];
        qf[kk][1] = Pu[base + 8 * ASTR];
        qf[kk][2] = Pu[base + 4];
        qf[kk][3] = Pu[base + 8 * ASTR + 4];
    }

    float oacc[8][4];
#pragma unroll
    for (int nt = 0; nt < 8; nt++)
#pragma unroll
        for (int q = 0; q < 4; q++) oacc[nt][q] = 0.f;
    float mA = -INFINITY, mB = -INFINITY, lA = 0.f, lB = 0.f;

    int grA = q0 + rA, grB = grA + 8;
    const int nkb = qi + 1;

    for (int kb = 0; kb < nkb; kb++) {
        __syncthreads();   // protect Ks/Vt reuse
        // load K (natural) and V (transposed), tf32-rounded
#pragma unroll
        for (int i = 0; i < 8; i++) {
            int idx = tid + i * 128;
            int n = idx >> 4, c4 = (idx & 15) << 2;
            float4 kv = *(const float4*)(Kp + (size_t)(kb * 64 + n) * CK + c4);
            float4 kw;
            kw.x = f2tff(kv.x); kw.y = f2tff(kv.y);
            kw.z = f2tff(kv.z); kw.w = f2tff(kv.w);
            *(float4*)&Ks[n * ASTR + c4] = kw;
            float4 vv = *(const float4*)(Vp + (size_t)(kb * 64 + n) * CK + c4);
            Vt[(c4 + 0) * ASTR + n] = f2tff(vv.x);
            Vt[(c4 + 1) * ASTR + n] = f2tff(vv.y);
            Vt[(c4 + 2) * ASTR + n] = f2tff(vv.z);
            Vt[(c4 + 3) * ASTR + n] = f2tff(vv.w);
        }
        __syncthreads();

        // S = Q K^T  (warp: 16 x 64)
        float sacc[8][4];
#pragma unroll
        for (int nt = 0; nt < 8; nt++)
#pragma unroll
            for (int q = 0; q < 4; q++) sacc[nt][q] = 0.f;
        const uint32_t* Ku = (const uint32_t*)Ks;
#pragma unroll
        for (int kk = 0; kk < 8; kk++) {
#pragma unroll
            for (int nt = 0; nt < 8; nt++) {
                int r = (8 * nt + gid) * ASTR + 8 * kk + tig;
                uint32_t b[2] = {Ku[r], Ku[r + 4]};
                mma_tf32_16n8k8(sacc[nt], qf[kk], b);
            }
        }

        // causal mask (register)
        if (kb * 64 + 63 > q0 + wid * 16) {
#pragma unroll
            for (int nt = 0; nt < 8; nt++) {
                int c0 = kb * 64 + 8 * nt + 2 * tig;
                if (c0     > grA) sacc[nt][0] = -INFINITY;
                if (c0 + 1 > grA) sacc[nt][1] = -INFINITY;
                if (c0     > grB) sacc[nt][2] = -INFINITY;
                if (c0 + 1 > grB) sacc[nt][3] = -INFINITY;
            }
        }

        // online softmax (registers; rows A and B)
        float mxA = -INFINITY, mxB = -INFINITY;
#pragma unroll
        for (int nt = 0; nt < 8; nt++) {
            mxA = fmaxf(mxA, fmaxf(sacc[nt][0], sacc[nt][1]));
            mxB = fmaxf(mxB, fmaxf(sacc[nt][2], sacc[nt][3]));
        }
        mxA = fmaxf(mxA, __shfl_xor_sync(0xffffffffu, mxA, 1));
        mxA = fmaxf(mxA, __shfl_xor_sync(0xffffffffu, mxA, 2));
        mxB = fmaxf(mxB, __shfl_xor_sync(0xffffffffu, mxB, 1));
        mxB = fmaxf(mxB, __shfl_xor_sync(0xffffffffu, mxB, 2));
        float mnA = fmaxf(mA, mxA), mnB = fmaxf(mB, mxB);
        float aA = __expf(mA - mnA), aB = __expf(mB - mnB);
        lA *= aA; lB *= aB;
        float* prA = &Ps[(wid * 16 + gid) * ASTR];
        float* prB = prA + 8 * ASTR;
#pragma unroll
        for (int nt = 0; nt < 8; nt++) {
            float p0 = __expf(sacc[nt][0] - mnA);
            float p1 = __expf(sacc[nt][1] - mnA);
            float p2 = __expf(sacc[nt][2] - mnB);
            float p3 = __expf(sacc[nt][3] - mnB);
            lA += p0 + p1; lB += p2 + p3;
            int c = 8 * nt + 2 * tig;
            *(float2*)&prA[c] = make_float2(f2tff(p0), f2tff(p1));
            *(float2*)&prB[c] = make_float2(f2tff(p2), f2tff(p3));
            oacc[nt][0] *= aA; oacc[nt][1] *= aA;
            oacc[nt][2] *= aB; oacc[nt][3] *= aB;
        }
        mA = mnA; mB = mnB;
        __syncwarp();

        // O += P V  (A = P own rows from smem, B = Vt)
        const uint32_t* Vu = (const uint32_t*)Vt;
#pragma unroll
        for (int kk = 0; kk < 8; kk++) {
            int base = rA * ASTR + 8 * kk + tig;
            uint32_t a[4] = {Pu[base], Pu[base + 8 * ASTR],
                             Pu[base + 4], Pu[base + 8 * ASTR + 4]};
#pragma unroll
            for (int nt = 0; nt < 8; nt++) {
                int r = (8 * nt + gid) * ASTR + 8 * kk + tig;
                uint32_t b[2] = {Vu[r], Vu[r + 4]};
                mma_tf32_16n8k8(oacc[nt], a, b);
            }
        }
        __syncwarp();
    }

    // finalize: reduce l over quad, scale, write concat output (tf32)
    lA += __shfl_xor_sync(0xffffffffu, lA, 1);
    lA += __shfl_xor_sync(0xffffffffu, lA, 2);
    lB += __shfl_xor_sync(0xffffffffu, lB, 1);
    lB += __shfl_xor_sync(0xffffffffu, lB, 2);
    float iA = 1.f / lA, iB = 1.f / lB;

    int b = bh >> 4, h = bh & 15;
    size_t baseA = ((size_t)(b * CT + grA)) * CD + h * 64;
    size_t baseB = ((size_t)(b * CT + grB)) * CD + h * 64;
#pragma unroll
    for (int nt = 0; nt < 8; nt++) {
        int c = 8 * nt + 2 * tig;
        *(float2*)&g_oc[baseA + c] =
            make_float2(f2tff(oacc[nt][0] * iA), f2tff(oacc[nt][1] * iA));
        *(float2*)&g_oc[baseB + c] =
            make_float2(f2tff(oacc[nt][2] * iB), f2tff(oacc[nt][3] * iB));
    }
}

// ============================= launch ==============================
extern "C" void kernel_launch(void* const* d_in, const int* in_sizes, int n_in,
                              void* d_out, int out_size) {
    (void)in_sizes; (void)n_in; (void)out_size;
    const float* x   = (const float*)d_in[0];
    const float* Wq  = (const float*)d_in[1];
    const float* Wk  = (const float*)d_in[2];
    const float* Wv  = (const float*)d_in[3];
    const float* Wo  = (const float*)d_in[4];
    const float* bo  = (const float*)d_in[5];
    const float* W1  = (const float*)d_in[6];
    const float* b1  = (const float*)d_in[7];
    const float* W2  = (const float*)d_in[8];
    const float* b2  = (const float*)d_in[9];
    const float* g1  = (const float*)d_in[10];
    const float* be1 = (const float*)d_in[11];
    const float* g2  = (const float*)d_in[12];
    const float* be2 = (const float*)d_in[13];
    float* out = (float*)d_out;

    cudaFuncSetAttribute(k_attn_mma, cudaFuncAttributeMaxDynamicSharedMemorySize, ATTN_SMEM_BYTES);
    cudaFuncSetAttribute(k_gemm<0>, cudaFuncAttributeMaxDynamicSharedMemorySize, GEMM_SMEM);
    cudaFuncSetAttribute(k_gemm<1>, cudaFuncAttributeMaxDynamicSharedMemorySize, GEMM_SMEM);
    cudaFuncSetAttribute(k_gemm<2>, cudaFuncAttributeMaxDynamicSharedMemorySize, GEMM_SMEM);
    cudaFuncSetAttribute(k_gemm<3>, cudaFuncAttributeMaxDynamicSharedMemorySize, GEMM_SMEM);

    float* g_qkvwt_p; cudaGetSymbolAddress((void**)&g_qkvwt_p, g_qkvwt);
    float* g_wot_p;   cudaGetSymbolAddress((void**)&g_wot_p, g_wot);
    float* g_w1t_p;   cudaGetSymbolAddress((void**)&g_w1t_p, g_w1t);
    float* g_w2t_p;   cudaGetSymbolAddress((void**)&g_w2t_p, g_w2t);
    float* g_h1_p;    cudaGetSymbolAddress((void**)&g_h1_p, g_h1);
    float* g_oc_p;    cudaGetSymbolAddress((void**)&g_oc_p, g_oc);
    float* g_x2_p;    cudaGetSymbolAddress((void**)&g_x2_p, g_x2);
    float* g_h2_p;    cudaGetSymbolAddress((void**)&g_h2_p, g_h2);
    float* g_ff_p;    cudaGetSymbolAddress((void**)&g_ff_p, g_ff);

    // weight transposes -> [N][K] tf32
    k_qkvw_tr<<<dim3(CK / 32, CD / 32, 48), dim3(32, 8)>>>(Wq, Wk, Wv);
    k_tr<<<dim3(CD / 32, CD / 32), dim3(32, 8)>>>(Wo, g_wot_p, CD, CD);
    k_tr<<<dim3(CDFF / 32, CD / 32), dim3(32, 8)>>>(W1, g_w1t_p, CD, CDFF);
    k_tr<<<dim3(CD / 32, CDFF / 32), dim3(32, 8)>>>(W2, g_w2t_p, CDFF, CD);

    k_ln1<<<CBT, 256>>>(x, g1, be1);
    // QKV: [4096 x 3072]
    k_gemm<0><<<dim3(CBT / 128, 3 * CD / 128), 256, GEMM_SMEM>>>(
        g_h1_p, CD, g_qkvwt_p, CD, nullptr, nullptr, nullptr, 0);
    k_attn_mma<<<dim3(CT / 64, CB * CH), 128, ATTN_SMEM_BYTES>>>();
    // Wo + residual
    k_gemm<1><<<dim3(CBT / 128, CD / 128), 256, GEMM_SMEM>>>(
        g_oc_p, CD, g_wot_p, CD, bo, x, g_x2_p, CD);
    k_ln2<<<CBT, 256>>>(g2, be2);
    // FF1 + gelu
    k_gemm<2><<<dim3(CBT / 128, CDFF / 128), 256, GEMM_SMEM>>>(
        g_h2_p, CD, g_w1t_p, CD, b1, nullptr, g_ff_p, CDFF);
    // FF2 + residual -> out
    k_gemm<3><<<dim3(CBT / 128, CD / 128), 256, GEMM_SMEM>>>(
        g_ff_p, CDFF, g_w2t_p, CDFF, b2, g_x2_p, out, CD);
}